// round 5
// baseline (speedup 1.0000x reference)
#include <cuda_runtime.h>
#include <cstdint>

typedef unsigned long long ull;

static constexpr int BATCH  = 16;
static constexpr int NPTS   = 2048;
static constexpr int TOTAL  = BATCH * NPTS;    // 32768
static constexpr int KNN    = 6;
static constexpr int NSPLIT = 4;
static constexpr int CHUNK  = NPTS / NSPLIT;   // 512

// ---------------- scratch (device globals; no cudaMalloc allowed) ----------
__device__ float g_x0[TOTAL * 64];
__device__ float g_x1[TOTAL * 32];
__device__ float g_sq[TOTAL];
__device__ int   g_knn[TOTAL * KNN];
__device__ float g_pd[TOTAL * NSPLIT * KNN];
__device__ int   g_pi[TOTAL * NSPLIT * KNN];

// ---------------- f32x2 helpers --------------------------------------------
__device__ __forceinline__ ull fma2(ull a, ull b, ull c) {
    ull d;
    asm("fma.rn.f32x2 %0, %1, %2, %3;" : "=l"(d) : "l"(a), "l"(b), "l"(c));
    return d;
}
__device__ __forceinline__ ull pack2(float x, float y) {
    ull r;
    asm("mov.b64 %0, {%1, %2};" : "=l"(r) : "f"(x), "f"(y));
    return r;
}
__device__ __forceinline__ void unpack2(ull v, float& x, float& y) {
    asm("mov.b64 {%0, %1}, %2;" : "=f"(x), "=f"(y) : "l"(v));
}

// ---------------- squared norms --------------------------------------------
template <int C>
__global__ void sq_kernel(const float* __restrict__ x, float* __restrict__ sq) {
    int p = blockIdx.x * 256 + threadIdx.x;
    if (p >= TOTAL) return;
    const float4* xp = reinterpret_cast<const float4*>(x + (size_t)p * C);
    float s = 0.f;
#pragma unroll
    for (int i = 0; i < C / 4; i++) {
        float4 v = xp[i];
        s += v.x * v.x + v.y * v.y + v.z * v.z + v.w * v.w;
    }
    sq[p] = s;
}

// ---------------- partial kNN over one candidate chunk ---------------------
// Q queries per thread (Q=2 for C=32, Q=1 for C=64). 16-candidate tiles
// double-buffered in smem; compute in sub-tiles of 8 to cap accumulator regs.
// Rank by csq - 2*dot (query norm cancels in all comparisons).
template <int C, int Q>
__global__ void __launch_bounds__(128)
knn_part_kernel(const float* __restrict__ x,
                const float* __restrict__ sq,
                float* __restrict__ pd, int* __restrict__ pi) {
    constexpr int CT  = 16;            // candidates staged per round
    constexpr int ST  = 8;             // candidates per compute sub-tile
    constexpr int SP  = CT * 2 + 4;    // float stride per feature-pair row
    constexpr int LPT = CT * C / (128 * 4);  // float4 loads/thread/round
    __shared__ __align__(16) float scs[2][(C / 2) * SP];
    __shared__ float ssq[2][CT];

    const int b     = blockIdx.y;
    const int chunk = blockIdx.z;
    const int tid   = threadIdx.x;
    const float* xb = x + (size_t)b * NPTS * C;
    const float* sb = sq + b * NPTS;

    int qloc[Q];
    ull qf[Q][C / 2];
#pragma unroll
    for (int r = 0; r < Q; r++) {
        qloc[r] = blockIdx.x * (128 * Q) + r * 128 + tid;
#pragma unroll
        for (int ip = 0; ip < C / 4; ip++) {
            float4 v = *reinterpret_cast<const float4*>(
                xb + (size_t)qloc[r] * C + ip * 4);
            qf[r][2 * ip]     = pack2(v.x, v.y);
            qf[r][2 * ip + 1] = pack2(v.z, v.w);
        }
    }

    const float INF = __int_as_float(0x7f800000);
    float kd[Q][6];
    int   ki[Q][6];
#pragma unroll
    for (int r = 0; r < Q; r++)
#pragma unroll
        for (int j = 0; j < 6; j++) { kd[r][j] = INF; ki[r][j] = 0; }

    const int m_beg = chunk * CHUNK;
    constexpr int TILES = CHUNK / CT;

    float4 v[LPT];
    float  sv;

    // prologue: load + store tile 0
#pragma unroll
    for (int n = 0; n < LPT; n++) {
        int f  = tid * 4 + n * 512;
        int mm = f / C, i = f % C;
        v[n] = *reinterpret_cast<const float4*>(xb + (size_t)(m_beg + mm) * C + i);
    }
    if (tid < CT) sv = sb[m_beg + tid];
#pragma unroll
    for (int n = 0; n < LPT; n++) {
        int f  = tid * 4 + n * 512;
        int mm = f / C, i = f % C;
        *reinterpret_cast<float2*>(&scs[0][(i >> 1) * SP + mm * 2])       = make_float2(v[n].x, v[n].y);
        *reinterpret_cast<float2*>(&scs[0][((i >> 1) + 1) * SP + mm * 2]) = make_float2(v[n].z, v[n].w);
    }
    if (tid < CT) ssq[0][tid] = sv;
    __syncthreads();

    for (int t = 0; t < TILES; t++) {
        const int m0  = m_beg + t * CT;
        const int cur = t & 1;

        // issue next tile's global loads early (overlap with fma block)
        if (t + 1 < TILES) {
#pragma unroll
            for (int n = 0; n < LPT; n++) {
                int f  = tid * 4 + n * 512;
                int mm = f / C, i = f % C;
                v[n] = *reinterpret_cast<const float4*>(
                    xb + (size_t)(m0 + CT + mm) * C + i);
            }
            if (tid < CT) sv = sb[m0 + CT + tid];
        }

#pragma unroll
        for (int sub = 0; sub < 2; sub++) {
            ull acc[Q][ST];
#pragma unroll
            for (int r = 0; r < Q; r++)
#pragma unroll
                for (int mm = 0; mm < ST; mm++) acc[r][mm] = 0ull;

#pragma unroll
            for (int ip = 0; ip < C / 2; ip++) {
                const ulonglong2* base = reinterpret_cast<const ulonglong2*>(
                    &scs[cur][ip * SP + sub * ST * 2]);
#pragma unroll
                for (int mm2 = 0; mm2 < ST / 2; mm2++) {
                    ulonglong2 cc = base[mm2];
#pragma unroll
                    for (int r = 0; r < Q; r++) {
                        acc[r][2 * mm2]     = fma2(qf[r][ip], cc.x, acc[r][2 * mm2]);
                        acc[r][2 * mm2 + 1] = fma2(qf[r][ip], cc.y, acc[r][2 * mm2 + 1]);
                    }
                }
            }

#pragma unroll
            for (int mm = 0; mm < ST; mm++) {
                const int   m  = m0 + sub * ST + mm;
                const float cs = ssq[cur][sub * ST + mm];
#pragma unroll
                for (int r = 0; r < Q; r++) {
                    float lo, hi;
                    unpack2(acc[r][mm], lo, hi);
                    float d = fmaf(-2.f, lo + hi, cs);
                    if (m != qloc[r] && d < kd[r][5]) {   // strict < keeps lower idx on ties
                        kd[r][5] = d; ki[r][5] = m;
#pragma unroll
                        for (int j = 5; j > 0; j--) {
                            if (kd[r][j] < kd[r][j - 1]) {
                                float td = kd[r][j]; kd[r][j] = kd[r][j - 1]; kd[r][j - 1] = td;
                                int   ti = ki[r][j]; ki[r][j] = ki[r][j - 1]; ki[r][j - 1] = ti;
                            }
                        }
                    }
                }
            }
        }

        // store next tile into the other buffer
        if (t + 1 < TILES) {
            const int nxt = cur ^ 1;
#pragma unroll
            for (int n = 0; n < LPT; n++) {
                int f  = tid * 4 + n * 512;
                int mm = f / C, i = f % C;
                *reinterpret_cast<float2*>(&scs[nxt][(i >> 1) * SP + mm * 2])       = make_float2(v[n].x, v[n].y);
                *reinterpret_cast<float2*>(&scs[nxt][((i >> 1) + 1) * SP + mm * 2]) = make_float2(v[n].z, v[n].w);
            }
            if (tid < CT) ssq[nxt][tid] = sv;
        }
        __syncthreads();
    }

#pragma unroll
    for (int r = 0; r < Q; r++) {
        const int base = ((b * NPTS + qloc[r]) * NSPLIT + chunk) * KNN;
#pragma unroll
        for (int k = 0; k < KNN; k++) {
            pd[base + k] = kd[r][k];
            pi[base + k] = b * NPTS + ki[r][k];
        }
    }
}

// ---------------- merge NSPLIT partial top-6 lists --------------------------
__global__ void knn_merge_kernel(const float* __restrict__ pd,
                                 const int* __restrict__ pi,
                                 int* __restrict__ knn) {
    int p = blockIdx.x * 256 + threadIdx.x;
    if (p >= TOTAL) return;
    const float INF = __int_as_float(0x7f800000);
    float kd[6] = {INF, INF, INF, INF, INF, INF};
    int   ki[6] = {0, 0, 0, 0, 0, 0};
    const int base = p * NSPLIT * KNN;
#pragma unroll
    for (int e = 0; e < NSPLIT * KNN; e++) {
        float d = pd[base + e];
        int   i = pi[base + e];
        if (d < kd[5]) {
            kd[5] = d; ki[5] = i;
#pragma unroll
            for (int j = 5; j > 0; j--) {
                if (kd[j] < kd[j - 1]) {
                    float td = kd[j]; kd[j] = kd[j - 1]; kd[j - 1] = td;
                    int   ti = ki[j]; ki[j] = ki[j - 1]; ki[j - 1] = ti;
                }
            }
        }
    }
#pragma unroll
    for (int k = 0; k < KNN; k++) knn[p * KNN + k] = ki[k];
}

// ---------------- edge MLP + max over K + (residual) + relu ----------------
// 4 warps/block share the staged weights; warp handles 8 points (pairs of 2);
// edges processed in halves of 3 to cap live accumulator registers at
// <=128 regs -> 4 blocks/SM (16 warps). xi@W1-front computed once per point.
template <int CIN, int H, int COUT, bool RES>
__global__ void __launch_bounds__(128, 4)
edge_kernel(const float* __restrict__ x,
            const int* __restrict__ knn,
            const float* __restrict__ W1, const float* __restrict__ b1,
            const float* __restrict__ W2, const float* __restrict__ b2,
            const float* __restrict__ res, float* __restrict__ out) {
    constexpr int WPB = 4;            // warps per block
    constexpr int PPW = 8;            // points per warp
    constexpr int PB  = 2;            // points processed together
    constexpr int KH  = 3;            // edges processed per half
    constexpr int CH  = H / 32;       // h1 channels per lane
    constexpr int CO  = COUT / 32;    // out channels per lane
    constexpr int RIN = CIN / 32;     // input features per lane

    __shared__ ull W1p[CIN * H];              // pair-row q -> rows (2q,2q+1)
    __shared__ ull W2p[(H / 2) * COUT];
    __shared__ __align__(16) ull xiu[WPB][PB][CIN / 2];
    __shared__ __align__(16) ull dgu[WPB][PB][KH][CIN / 2];
    __shared__ __align__(16) ull hbu[WPB][PB][KH][H / 2];

    const int tid  = threadIdx.x;
    const int w    = tid >> 5;
    const int lane = tid & 31;

    for (int idx = tid; idx < CIN * H; idx += 128) {
        int qq = idx / H, c = idx % H;
        W1p[idx] = pack2(W1[(2 * qq) * H + c], W1[(2 * qq + 1) * H + c]);
    }
    for (int idx = tid; idx < (H / 2) * COUT; idx += 128) {
        int qq = idx / COUT, c = idx % COUT;
        W2p[idx] = pack2(W2[(2 * qq) * COUT + c], W2[(2 * qq + 1) * COUT + c]);
    }
    __syncthreads();

    float b1v[CH], b2v[CO];
#pragma unroll
    for (int cc = 0; cc < CH; cc++) b1v[cc] = b1[lane + 32 * cc];
#pragma unroll
    for (int cc = 0; cc < CO; cc++) b2v[cc] = b2[lane + 32 * cc];

    const float NINF = __int_as_float(0xff800000);
    const int p0 = (blockIdx.x * WPB + w) * PPW;

    for (int pt = 0; pt < PPW; pt += PB) {
        // xi into per-warp smem (and regs)
        float xr[PB][RIN];
#pragma unroll
        for (int pp = 0; pp < PB; pp++) {
            const int P = p0 + pt + pp;
            float* xif = reinterpret_cast<float*>(xiu[w][pp]);
#pragma unroll
            for (int r = 0; r < RIN; r++) {
                xr[pp][r] = x[(size_t)P * CIN + lane + 32 * r];
                xif[lane + 32 * r] = xr[pp][r];
            }
        }
        __syncwarp();

        // edge-invariant half: xi @ W1[:CIN]
        ull ab[PB][CH];
#pragma unroll
        for (int pp = 0; pp < PB; pp++)
#pragma unroll
            for (int cc = 0; cc < CH; cc++) ab[pp][cc] = 0ull;
#pragma unroll
        for (int ip = 0; ip < CIN / 2; ip++) {
            ull wv[CH];
#pragma unroll
            for (int cc = 0; cc < CH; cc++)
                wv[cc] = W1p[ip * H + lane + 32 * cc];
#pragma unroll
            for (int pp = 0; pp < PB; pp++) {
                ull xv = xiu[w][pp][ip];
#pragma unroll
                for (int cc = 0; cc < CH; cc++)
                    ab[pp][cc] = fma2(xv, wv[cc], ab[pp][cc]);
            }
        }

        float best[PB][CO];
#pragma unroll
        for (int pp = 0; pp < PB; pp++)
#pragma unroll
            for (int cc = 0; cc < CO; cc++) best[pp][cc] = NINF;

#pragma unroll
        for (int kh = 0; kh < KNN / KH; kh++) {
            // neighbor diffs for this half's edges
#pragma unroll
            for (int pp = 0; pp < PB; pp++) {
                const int P = p0 + pt + pp;
#pragma unroll
                for (int kk = 0; kk < KH; kk++) {
                    int j = knn[P * KNN + kh * KH + kk];
                    float* dgf = reinterpret_cast<float*>(dgu[w][pp][kk]);
#pragma unroll
                    for (int r = 0; r < RIN; r++)
                        dgf[lane + 32 * r] =
                            x[(size_t)j * CIN + lane + 32 * r] - xr[pp][r];
                }
            }
            __syncwarp();

            // stage 1 per edge: h = relu(ab + (xj-xi) @ W1[CIN:] + b1)
            ull a2[PB][KH][CH];
#pragma unroll
            for (int pp = 0; pp < PB; pp++)
#pragma unroll
                for (int kk = 0; kk < KH; kk++)
#pragma unroll
                    for (int cc = 0; cc < CH; cc++) a2[pp][kk][cc] = ab[pp][cc];
#pragma unroll
            for (int ip = 0; ip < CIN / 2; ip++) {
                ull wv[CH];
#pragma unroll
                for (int cc = 0; cc < CH; cc++)
                    wv[cc] = W1p[(CIN / 2 + ip) * H + lane + 32 * cc];
#pragma unroll
                for (int pp = 0; pp < PB; pp++)
#pragma unroll
                    for (int kk = 0; kk < KH; kk++) {
                        ull dv = dgu[w][pp][kk][ip];
#pragma unroll
                        for (int cc = 0; cc < CH; cc++)
                            a2[pp][kk][cc] = fma2(dv, wv[cc], a2[pp][kk][cc]);
                    }
            }
#pragma unroll
            for (int pp = 0; pp < PB; pp++)
#pragma unroll
                for (int kk = 0; kk < KH; kk++) {
                    float* hbf = reinterpret_cast<float*>(hbu[w][pp][kk]);
#pragma unroll
                    for (int cc = 0; cc < CH; cc++) {
                        float lo, hi;
                        unpack2(a2[pp][kk][cc], lo, hi);
                        hbf[lane + 32 * cc] = fmaxf(b1v[cc] + lo + hi, 0.f);
                    }
                }
            __syncwarp();

            // stage 2: o = h1 @ W2 + b2, fold into running max
            ull o2[PB][KH][CO];
#pragma unroll
            for (int pp = 0; pp < PB; pp++)
#pragma unroll
                for (int kk = 0; kk < KH; kk++)
#pragma unroll
                    for (int cc = 0; cc < CO; cc++) o2[pp][kk][cc] = 0ull;
#pragma unroll
            for (int hp = 0; hp < H / 2; hp++) {
                ull wv[CO];
#pragma unroll
                for (int cc = 0; cc < CO; cc++)
                    wv[cc] = W2p[hp * COUT + lane + 32 * cc];
#pragma unroll
                for (int pp = 0; pp < PB; pp++)
#pragma unroll
                    for (int kk = 0; kk < KH; kk++) {
                        ull hv = hbu[w][pp][kk][hp];
#pragma unroll
                        for (int cc = 0; cc < CO; cc++)
                            o2[pp][kk][cc] = fma2(hv, wv[cc], o2[pp][kk][cc]);
                    }
            }
#pragma unroll
            for (int pp = 0; pp < PB; pp++)
#pragma unroll
                for (int kk = 0; kk < KH; kk++)
#pragma unroll
                    for (int cc = 0; cc < CO; cc++) {
                        float lo, hi;
                        unpack2(o2[pp][kk][cc], lo, hi);
                        best[pp][cc] = fmaxf(best[pp][cc], b2v[cc] + lo + hi);
                    }
            __syncwarp();
        }

#pragma unroll
        for (int pp = 0; pp < PB; pp++) {
            const int P = p0 + pt + pp;
#pragma unroll
            for (int cc = 0; cc < CO; cc++) {
                int c = lane + 32 * cc;
                float vv = best[pp][cc];
                if (RES) vv += res[(size_t)P * COUT + c];
                out[(size_t)P * COUT + c] = fmaxf(vv, 0.f);
            }
        }
    }
}

// ---------------- launch ----------------------------------------------------
extern "C" void kernel_launch(void* const* d_in, const int* in_sizes, int n_in,
                              void* d_out, int out_size) {
    const float* x    = (const float*)d_in[0];
    const float* W1_0 = (const float*)d_in[2];
    const float* b1_0 = (const float*)d_in[3];
    const float* W2_0 = (const float*)d_in[4];
    const float* b2_0 = (const float*)d_in[5];
    const float* W1_1 = (const float*)d_in[6];
    const float* b1_1 = (const float*)d_in[7];
    const float* W2_1 = (const float*)d_in[8];
    const float* b2_1 = (const float*)d_in[9];
    const float* W1_2 = (const float*)d_in[10];
    const float* b1_2 = (const float*)d_in[11];
    const float* W2_2 = (const float*)d_in[12];
    const float* b2_2 = (const float*)d_in[13];
    float* out = (float*)d_out;

    float *px0, *px1, *psq, *ppd;
    int *pknn, *ppi;
    cudaGetSymbolAddress((void**)&px0, g_x0);
    cudaGetSymbolAddress((void**)&px1, g_x1);
    cudaGetSymbolAddress((void**)&psq, g_sq);
    cudaGetSymbolAddress((void**)&pknn, g_knn);
    cudaGetSymbolAddress((void**)&ppd, g_pd);
    cudaGetSymbolAddress((void**)&ppi, g_pi);

    dim3 knn_grid32(NPTS / 256, BATCH, NSPLIT);   // Q=2
    dim3 knn_grid64(NPTS / 128, BATCH, NSPLIT);   // Q=1
    const int edge_grid = TOTAL / (4 * 8);        // WPB*PPW points per block

    // ---- layer 0: x(32) -> x0(64), relu
    sq_kernel<32><<<TOTAL / 256, 256>>>(x, psq);
    knn_part_kernel<32, 2><<<knn_grid32, 128>>>(x, psq, ppd, ppi);
    knn_merge_kernel<<<TOTAL / 256, 256>>>(ppd, ppi, pknn);
    edge_kernel<32, 64, 64, false><<<edge_grid, 128>>>(
        x, pknn, W1_0, b1_0, W2_0, b2_0, nullptr, px0);

    // ---- layer 1: x0(64) -> x1(32), relu
    sq_kernel<64><<<TOTAL / 256, 256>>>(px0, psq);
    knn_part_kernel<64, 1><<<knn_grid64, 128>>>(px0, psq, ppd, ppi);
    knn_merge_kernel<<<TOTAL / 256, 256>>>(ppd, ppi, pknn);
    edge_kernel<64, 32, 32, false><<<edge_grid, 128>>>(
        px0, pknn, W1_1, b1_1, W2_1, b2_1, nullptr, px1);

    // ---- layer 2: x1(32) -> out(64) = relu(conv + x0)
    sq_kernel<32><<<TOTAL / 256, 256>>>(px1, psq);
    knn_part_kernel<32, 2><<<knn_grid32, 128>>>(px1, psq, ppd, ppi);
    knn_merge_kernel<<<TOTAL / 256, 256>>>(ppd, ppi, pknn);
    edge_kernel<32, 64, 64, true><<<edge_grid, 128>>>(
        px1, pknn, W1_2, b1_2, W2_2, b2_2, px0, out);
}

// round 6
// speedup vs baseline: 1.3603x; 1.3603x over previous
#include <cuda_runtime.h>
#include <cstdint>

typedef unsigned long long ull;

static constexpr int BATCH  = 16;
static constexpr int NPTS   = 2048;
static constexpr int TOTAL  = BATCH * NPTS;    // 32768
static constexpr int KNN    = 6;
static constexpr int NSPLIT = 4;
static constexpr int CHUNK  = NPTS / NSPLIT;   // 512

// ---------------- scratch (device globals; no cudaMalloc allowed) ----------
__device__ float g_x0[TOTAL * 64];
__device__ float g_x1[TOTAL * 32];
__device__ float g_sq[TOTAL];
__device__ int   g_knn[TOTAL * KNN];
__device__ float g_pd[TOTAL * NSPLIT * KNN];
__device__ int   g_pi[TOTAL * NSPLIT * KNN];

// ---------------- f32x2 helpers --------------------------------------------
__device__ __forceinline__ ull fma2(ull a, ull b, ull c) {
    ull d;
    asm("fma.rn.f32x2 %0, %1, %2, %3;" : "=l"(d) : "l"(a), "l"(b), "l"(c));
    return d;
}
__device__ __forceinline__ ull pack2(float x, float y) {
    ull r;
    asm("mov.b64 %0, {%1, %2};" : "=l"(r) : "f"(x), "f"(y));
    return r;
}
__device__ __forceinline__ void unpack2(ull v, float& x, float& y) {
    asm("mov.b64 {%0, %1}, %2;" : "=f"(x), "=f"(y) : "l"(v));
}

// ---------------- squared norms (input layer only) -------------------------
template <int C>
__global__ void sq_kernel(const float* __restrict__ x, float* __restrict__ sq) {
    int p = blockIdx.x * 256 + threadIdx.x;
    if (p >= TOTAL) return;
    const float4* xp = reinterpret_cast<const float4*>(x + (size_t)p * C);
    float s = 0.f;
#pragma unroll
    for (int i = 0; i < C / 4; i++) {
        float4 v = xp[i];
        s += v.x * v.x + v.y * v.y + v.z * v.z + v.w * v.w;
    }
    sq[p] = s;
}

// ---------------- partial kNN over one candidate chunk ---------------------
// block: 128 queries of one batch; MT-candidate tiles staged in smem in
// feature-paired layout. MT=16 for C=32, MT=8 for C=64 (caps accumulator
// registers so the C=64 launch keeps ~5 blocks/SM resident).
// Rank by csq - 2*dot: the query's own norm cancels in every comparison.
template <int C, int MT>
__global__ void __launch_bounds__(128)
knn_part_kernel(const float* __restrict__ x,
                const float* __restrict__ sq,
                float* __restrict__ pd, int* __restrict__ pi) {
    constexpr int SP = MT * 2 + 4;     // float stride per feature-pair row
    static_assert(MT * C == 128 * 4, "one float4 per thread per tile");
    __shared__ __align__(16) float scs[(C / 2) * SP];
    __shared__ float ssq[MT];

    const int b     = blockIdx.y;
    const int chunk = blockIdx.z;
    const int tid   = threadIdx.x;
    const int q     = blockIdx.x * 128 + tid;
    const float* xb = x + (size_t)b * NPTS * C;
    const float* sb = sq + b * NPTS;

    // query features into packed-pair registers
    ull qf[C / 2];
#pragma unroll
    for (int ip = 0; ip < C / 4; ip++) {
        float4 v = *reinterpret_cast<const float4*>(xb + (size_t)q * C + ip * 4);
        qf[2 * ip]     = pack2(v.x, v.y);
        qf[2 * ip + 1] = pack2(v.z, v.w);
    }

    const float INF = __int_as_float(0x7f800000);
    float kd[6] = {INF, INF, INF, INF, INF, INF};
    int   ki[6] = {0, 0, 0, 0, 0, 0};

    const int m_beg = chunk * CHUNK;
    for (int m0 = m_beg; m0 < m_beg + CHUNK; m0 += MT) {
        __syncthreads();
        {
            int f  = tid * 4;
            int mm = f / C, i = f % C;
            float4 v = *reinterpret_cast<const float4*>(
                xb + (size_t)(m0 + mm) * C + i);
            *reinterpret_cast<float2*>(&scs[(i >> 1) * SP + mm * 2])       = make_float2(v.x, v.y);
            *reinterpret_cast<float2*>(&scs[((i >> 1) + 1) * SP + mm * 2]) = make_float2(v.z, v.w);
        }
        if (tid < MT) ssq[tid] = sb[m0 + tid];
        __syncthreads();

        ull acc[MT];
#pragma unroll
        for (int mm = 0; mm < MT; mm++) acc[mm] = 0ull;

#pragma unroll
        for (int ip = 0; ip < C / 2; ip++) {
            ull qv = qf[ip];
            const ulonglong2* base =
                reinterpret_cast<const ulonglong2*>(&scs[ip * SP]);
#pragma unroll
            for (int mm2 = 0; mm2 < MT / 2; mm2++) {
                ulonglong2 cc = base[mm2];
                acc[2 * mm2]     = fma2(qv, cc.x, acc[2 * mm2]);
                acc[2 * mm2 + 1] = fma2(qv, cc.y, acc[2 * mm2 + 1]);
            }
        }

#pragma unroll
        for (int mm = 0; mm < MT; mm++) {
            float lo, hi;
            unpack2(acc[mm], lo, hi);
            float d = fmaf(-2.f, lo + hi, ssq[mm]);   // csq - 2*dot
            int   m = m0 + mm;
            if (m != q && d < kd[5]) {   // strict < keeps lower index on ties
                kd[5] = d; ki[5] = m;
#pragma unroll
                for (int j = 5; j > 0; j--) {
                    if (kd[j] < kd[j - 1]) {
                        float td = kd[j]; kd[j] = kd[j - 1]; kd[j - 1] = td;
                        int   ti = ki[j]; ki[j] = ki[j - 1]; ki[j - 1] = ti;
                    }
                }
            }
        }
    }

    const int base = ((b * NPTS + q) * NSPLIT + chunk) * KNN;
#pragma unroll
    for (int k = 0; k < KNN; k++) {
        pd[base + k] = kd[k];
        pi[base + k] = b * NPTS + ki[k];
    }
}

// ---------------- merge NSPLIT partial top-6 lists --------------------------
// Entries arrive in chunk order (ascending candidate index ranges), each list
// ascending distance with ties already lower-index-first; strict-< insertion
// therefore reproduces global top_k tie-breaking for set membership.
__global__ void knn_merge_kernel(const float* __restrict__ pd,
                                 const int* __restrict__ pi,
                                 int* __restrict__ knn) {
    int p = blockIdx.x * 256 + threadIdx.x;
    if (p >= TOTAL) return;
    const float INF = __int_as_float(0x7f800000);
    float kd[6] = {INF, INF, INF, INF, INF, INF};
    int   ki[6] = {0, 0, 0, 0, 0, 0};
    const int base = p * NSPLIT * KNN;
#pragma unroll
    for (int e = 0; e < NSPLIT * KNN; e++) {
        float d = pd[base + e];
        int   i = pi[base + e];
        if (d < kd[5]) {
            kd[5] = d; ki[5] = i;
#pragma unroll
            for (int j = 5; j > 0; j--) {
                if (kd[j] < kd[j - 1]) {
                    float td = kd[j]; kd[j] = kd[j - 1]; kd[j - 1] = td;
                    int   ti = ki[j]; ki[j] = ki[j - 1]; ki[j - 1] = ti;
                }
            }
        }
    }
#pragma unroll
    for (int k = 0; k < KNN; k++) knn[p * KNN + k] = ki[k];
}

// ---------------- edge MLP + max over K + (residual) + relu ----------------
// warp per point-group (8 points, processed in pairs so each weight LDS feeds
// 2 points x 6 edges x CH fma2). xi half of stage-1 computed once per point.
// WSQ: fused output-row-norm write (feeds the next layer's kNN).
template <int CIN, int H, int COUT, bool RES, bool WSQ>
__global__ void __launch_bounds__(64)
edge_kernel(const float* __restrict__ x,
            const int* __restrict__ knn,
            const float* __restrict__ W1, const float* __restrict__ b1,
            const float* __restrict__ W2, const float* __restrict__ b2,
            const float* __restrict__ res, float* __restrict__ out,
            float* __restrict__ osq) {
    constexpr int WPB = 2;            // warps per block
    constexpr int PPW = 8;            // points per warp
    constexpr int PB  = 2;            // points processed together
    constexpr int CH  = H / 32;       // h1 channels per lane
    constexpr int CO  = COUT / 32;    // out channels per lane
    constexpr int RIN = CIN / 32;     // input features per lane

    __shared__ ull W1p[CIN * H];              // pair-row q -> rows (2q,2q+1)
    __shared__ ull W2p[(H / 2) * COUT];
    __shared__ __align__(16) ull xiu[WPB][PB][CIN / 2];
    __shared__ __align__(16) ull dgu[WPB][PB][KNN][CIN / 2];
    __shared__ __align__(16) ull hbu[WPB][PB][KNN][H / 2];

    const int tid  = threadIdx.x;
    const int w    = tid >> 5;
    const int lane = tid & 31;

    for (int idx = tid; idx < CIN * H; idx += 64) {
        int qq = idx / H, c = idx % H;
        W1p[idx] = pack2(W1[(2 * qq) * H + c], W1[(2 * qq + 1) * H + c]);
    }
    for (int idx = tid; idx < (H / 2) * COUT; idx += 64) {
        int qq = idx / COUT, c = idx % COUT;
        W2p[idx] = pack2(W2[(2 * qq) * COUT + c], W2[(2 * qq + 1) * COUT + c]);
    }
    __syncthreads();

    float b1v[CH], b2v[CO];
#pragma unroll
    for (int cc = 0; cc < CH; cc++) b1v[cc] = b1[lane + 32 * cc];
#pragma unroll
    for (int cc = 0; cc < CO; cc++) b2v[cc] = b2[lane + 32 * cc];

    const float NINF = __int_as_float(0xff800000);
    const int p0 = (blockIdx.x * WPB + w) * PPW;

    for (int pt = 0; pt < PPW; pt += PB) {
        // xi + neighbor diffs into per-warp smem for both points
        float xr[PB][RIN];
#pragma unroll
        for (int pp = 0; pp < PB; pp++) {
            const int P = p0 + pt + pp;
            float* xif = reinterpret_cast<float*>(xiu[w][pp]);
#pragma unroll
            for (int r = 0; r < RIN; r++) {
                xr[pp][r] = x[(size_t)P * CIN + lane + 32 * r];
                xif[lane + 32 * r] = xr[pp][r];
            }
#pragma unroll
            for (int k = 0; k < KNN; k++) {
                int j = knn[P * KNN + k];
                float* dgf = reinterpret_cast<float*>(dgu[w][pp][k]);
#pragma unroll
                for (int r = 0; r < RIN; r++)
                    dgf[lane + 32 * r] =
                        x[(size_t)j * CIN + lane + 32 * r] - xr[pp][r];
            }
        }
        __syncwarp();

        // stage 1 base: xi @ W1[:CIN] (edge-invariant, shared weight loads)
        ull ab[PB][CH];
#pragma unroll
        for (int pp = 0; pp < PB; pp++)
#pragma unroll
            for (int cc = 0; cc < CH; cc++) ab[pp][cc] = 0ull;
#pragma unroll
        for (int ip = 0; ip < CIN / 2; ip++) {
            ull wv[CH];
#pragma unroll
            for (int cc = 0; cc < CH; cc++)
                wv[cc] = W1p[ip * H + lane + 32 * cc];
#pragma unroll
            for (int pp = 0; pp < PB; pp++) {
                ull xv = xiu[w][pp][ip];
#pragma unroll
                for (int cc = 0; cc < CH; cc++)
                    ab[pp][cc] = fma2(xv, wv[cc], ab[pp][cc]);
            }
        }

        // stage 1 per edge: + (xj-xi) @ W1[CIN:]
        ull a2[PB][KNN][CH];
#pragma unroll
        for (int pp = 0; pp < PB; pp++)
#pragma unroll
            for (int k = 0; k < KNN; k++)
#pragma unroll
                for (int cc = 0; cc < CH; cc++) a2[pp][k][cc] = ab[pp][cc];
#pragma unroll
        for (int ip = 0; ip < CIN / 2; ip++) {
            ull wv[CH];
#pragma unroll
            for (int cc = 0; cc < CH; cc++)
                wv[cc] = W1p[(CIN / 2 + ip) * H + lane + 32 * cc];
#pragma unroll
            for (int pp = 0; pp < PB; pp++)
#pragma unroll
                for (int k = 0; k < KNN; k++) {
                    ull dv = dgu[w][pp][k][ip];
#pragma unroll
                    for (int cc = 0; cc < CH; cc++)
                        a2[pp][k][cc] = fma2(dv, wv[cc], a2[pp][k][cc]);
                }
        }
#pragma unroll
        for (int pp = 0; pp < PB; pp++)
#pragma unroll
            for (int k = 0; k < KNN; k++) {
                float* hbf = reinterpret_cast<float*>(hbu[w][pp][k]);
#pragma unroll
                for (int cc = 0; cc < CH; cc++) {
                    float lo, hi;
                    unpack2(a2[pp][k][cc], lo, hi);
                    hbf[lane + 32 * cc] = fmaxf(b1v[cc] + lo + hi, 0.f);
                }
            }
        __syncwarp();

        // stage 2: o = h1 @ W2 + b2, max over edges
        ull o2[PB][KNN][CO];
#pragma unroll
        for (int pp = 0; pp < PB; pp++)
#pragma unroll
            for (int k = 0; k < KNN; k++)
#pragma unroll
                for (int cc = 0; cc < CO; cc++) o2[pp][k][cc] = 0ull;
#pragma unroll
        for (int hp = 0; hp < H / 2; hp++) {
            ull wv[CO];
#pragma unroll
            for (int cc = 0; cc < CO; cc++)
                wv[cc] = W2p[hp * COUT + lane + 32 * cc];
#pragma unroll
            for (int pp = 0; pp < PB; pp++)
#pragma unroll
                for (int k = 0; k < KNN; k++) {
                    ull hv = hbu[w][pp][k][hp];
#pragma unroll
                    for (int cc = 0; cc < CO; cc++)
                        o2[pp][k][cc] = fma2(hv, wv[cc], o2[pp][k][cc]);
                }
        }
#pragma unroll
        for (int pp = 0; pp < PB; pp++) {
            const int P = p0 + pt + pp;
            float best[CO];
#pragma unroll
            for (int cc = 0; cc < CO; cc++) best[cc] = NINF;
#pragma unroll
            for (int k = 0; k < KNN; k++)
#pragma unroll
                for (int cc = 0; cc < CO; cc++) {
                    float lo, hi;
                    unpack2(o2[pp][k][cc], lo, hi);
                    best[cc] = fmaxf(best[cc], b2v[cc] + lo + hi);
                }
            float sq_acc = 0.f;
#pragma unroll
            for (int cc = 0; cc < CO; cc++) {
                int c = lane + 32 * cc;
                float v = best[cc];
                if (RES) v += res[(size_t)P * COUT + c];
                v = fmaxf(v, 0.f);
                out[(size_t)P * COUT + c] = v;
                if (WSQ) sq_acc = fmaf(v, v, sq_acc);
            }
            if (WSQ) {
                // warp-wide sum of per-lane channel squares
#pragma unroll
                for (int off = 16; off > 0; off >>= 1)
                    sq_acc += __shfl_xor_sync(0xffffffffu, sq_acc, off);
                if (lane == 0) osq[P] = sq_acc;
            }
        }
        __syncwarp();
    }
}

// ---------------- launch ----------------------------------------------------
extern "C" void kernel_launch(void* const* d_in, const int* in_sizes, int n_in,
                              void* d_out, int out_size) {
    const float* x    = (const float*)d_in[0];
    const float* W1_0 = (const float*)d_in[2];
    const float* b1_0 = (const float*)d_in[3];
    const float* W2_0 = (const float*)d_in[4];
    const float* b2_0 = (const float*)d_in[5];
    const float* W1_1 = (const float*)d_in[6];
    const float* b1_1 = (const float*)d_in[7];
    const float* W2_1 = (const float*)d_in[8];
    const float* b2_1 = (const float*)d_in[9];
    const float* W1_2 = (const float*)d_in[10];
    const float* b1_2 = (const float*)d_in[11];
    const float* W2_2 = (const float*)d_in[12];
    const float* b2_2 = (const float*)d_in[13];
    float* out = (float*)d_out;

    float *px0, *px1, *psq, *ppd;
    int *pknn, *ppi;
    cudaGetSymbolAddress((void**)&px0, g_x0);
    cudaGetSymbolAddress((void**)&px1, g_x1);
    cudaGetSymbolAddress((void**)&psq, g_sq);
    cudaGetSymbolAddress((void**)&pknn, g_knn);
    cudaGetSymbolAddress((void**)&ppd, g_pd);
    cudaGetSymbolAddress((void**)&ppi, g_pi);

    dim3 knn_grid(NPTS / 128, BATCH, NSPLIT);
    const int edge_grid = TOTAL / (2 * 8);   // WPB*PPW points per block

    // ---- layer 0: x(32) -> x0(64), relu (+ row norms for next kNN)
    sq_kernel<32><<<TOTAL / 256, 256>>>(x, psq);
    knn_part_kernel<32, 16><<<knn_grid, 128>>>(x, psq, ppd, ppi);
    knn_merge_kernel<<<TOTAL / 256, 256>>>(ppd, ppi, pknn);
    edge_kernel<32, 64, 64, false, true><<<edge_grid, 64>>>(
        x, pknn, W1_0, b1_0, W2_0, b2_0, nullptr, px0, psq);

    // ---- layer 1: x0(64) -> x1(32), relu (+ row norms for next kNN)
    knn_part_kernel<64, 8><<<knn_grid, 128>>>(px0, psq, ppd, ppi);
    knn_merge_kernel<<<TOTAL / 256, 256>>>(ppd, ppi, pknn);
    edge_kernel<64, 32, 32, false, true><<<edge_grid, 64>>>(
        px0, pknn, W1_1, b1_1, W2_1, b2_1, nullptr, px1, psq);

    // ---- layer 2: x1(32) -> out(64) = relu(conv + x0)
    knn_part_kernel<32, 16><<<knn_grid, 128>>>(px1, psq, ppd, ppi);
    knn_merge_kernel<<<TOTAL / 256, 256>>>(ppd, ppi, pknn);
    edge_kernel<32, 64, 64, true, false><<<edge_grid, 64>>>(
        px1, pknn, W1_2, b1_2, W2_2, b2_2, px0, out, nullptr);
}